// round 1
// baseline (speedup 1.0000x reference)
#include <cuda_runtime.h>
#include <cstdint>

#define BB   2
#define TT   2048
#define HH   16
#define DH   64
#define DD   1024          // HH*DH
#define BH   (BB*HH)       // 32
#define TILE 128
#define NT   (TT/TILE)     // 16
#define NPAIRS (NT*(NT+1)/2) // 136

// Scratch (allocation-free rule: __device__ globals)
__device__ float g_V [(size_t)BH * TT * DH];
__device__ float g_Sv[(size_t)BH * TT * DH];

// ---------------------------------------------------------------------------
// Kernel 1: normalize v rows, build S = A - A^T per head, compute Sv = v*S.
// grid (NT, BH), block 256. Each warp handles 16 rows.
// ---------------------------------------------------------------------------
__global__ __launch_bounds__(256) void prep_kernel(const float* __restrict__ x,
                                                   const float* __restrict__ A) {
    __shared__ float S[DH * DH];      // 16 KB
    __shared__ float vsm[8][DH];      // one row per warp

    const int bh = blockIdx.y;
    const int b  = bh / HH;
    const int h  = bh % HH;

    // S[d][e] = A[h][d][e] - A[h][e][d]
    for (int idx = threadIdx.x; idx < DH * DH; idx += 256) {
        const int d = idx >> 6, e = idx & 63;
        S[idx] = A[(size_t)h * DH * DH + idx] - A[(size_t)h * DH * DH + e * DH + d];
    }
    __syncthreads();

    const int warp = threadIdx.x >> 5;
    const int lane = threadIdx.x & 31;
    const int t0   = blockIdx.x * 128;

    for (int it = 0; it < 16; ++it) {
        const int t = t0 + warp * 16 + it;
        const float* xp = x + ((size_t)(b * TT + t)) * DD + h * DH;
        float v0 = xp[lane];
        float v1 = xp[lane + 32];
        float ss = v0 * v0 + v1 * v1;
        #pragma unroll
        for (int o = 16; o; o >>= 1) ss += __shfl_xor_sync(0xffffffffu, ss, o);
        const float scale = 1.0f / fmaxf(sqrtf(ss), 1e-12f);
        v0 *= scale; v1 *= scale;

        vsm[warp][lane]      = v0;
        vsm[warp][lane + 32] = v1;
        __syncwarp();

        float s0 = 0.f, s1 = 0.f;
        #pragma unroll
        for (int d = 0; d < DH; ++d) {
            const float vd = vsm[warp][d];
            s0 += vd * S[d * DH + lane];
            s1 += vd * S[d * DH + lane + 32];
        }
        const size_t base = ((size_t)bh * TT + t) * DH;
        g_V [base + lane]      = v0;
        g_V [base + lane + 32] = v1;
        g_Sv[base + lane]      = s0;
        g_Sv[base + lane + 32] = s1;
        __syncwarp();   // protect vsm before next iteration's overwrite
    }
}

// ---------------------------------------------------------------------------
// Kernel 2: W[t,s] = Sv[t,:] . V[s,:]  per (b,h), exploiting skew-symmetry.
// Upper-triangular 128x128 tiles only; mirror tile written as -W^T.
// grid (NPAIRS, BH), block 256, 8x8 micro-tile per thread, K=64 single pass.
// ---------------------------------------------------------------------------
__global__ __launch_bounds__(256) void wedge_kernel(float* __restrict__ out) {
    extern __shared__ float sm[];
    float* sA = sm;                 // [64][128] k-major: Sv tile (t rows)
    float* sB = sm + DH * TILE;     // [64][128] k-major: V  tile (s rows)

    const int bh = blockIdx.y;

    // map linear pair index -> (i <= j)
    int p = blockIdx.x;
    int i = 0;
    while (p >= NT - i) { p -= NT - i; ++i; }
    const int j  = i + p;
    const int i0 = i * TILE;
    const int j0 = j * TILE;

    const int tid = threadIdx.x;
    const float* Sv = g_Sv + (size_t)bh * TT * DH;
    const float* V  = g_V  + (size_t)bh * TT * DH;

    // Load tiles transposed into k-major smem. Mapping keeps warp lanes on
    // consecutive t for a fixed k-quad -> conflict-free STS.
    #pragma unroll
    for (int s = 0; s < 8; ++s) {
        const int f  = tid + s * 256;   // 0..2047 float4 slots
        const int k4 = f >> 7;          // 0..15
        const int t  = f & 127;
        const float4 a = *(const float4*)(Sv + (size_t)(i0 + t) * DH + k4 * 4);
        const float4 b = *(const float4*)(V  + (size_t)(j0 + t) * DH + k4 * 4);
        const int k = k4 * 4;
        sA[(k + 0) * TILE + t] = a.x;
        sA[(k + 1) * TILE + t] = a.y;
        sA[(k + 2) * TILE + t] = a.z;
        sA[(k + 3) * TILE + t] = a.w;
        sB[(k + 0) * TILE + t] = b.x;
        sB[(k + 1) * TILE + t] = b.y;
        sB[(k + 2) * TILE + t] = b.z;
        sB[(k + 3) * TILE + t] = b.w;
    }
    __syncthreads();

    const int tx = tid & 15;   // s (n) direction
    const int ty = tid >> 4;   // t (m) direction

    float acc[8][8];
    #pragma unroll
    for (int m = 0; m < 8; ++m)
        #pragma unroll
        for (int n = 0; n < 8; ++n) acc[m][n] = 0.f;

    #pragma unroll 8
    for (int k = 0; k < DH; ++k) {
        const float4 a0 = *(const float4*)&sA[k * TILE + ty * 4];
        const float4 a1 = *(const float4*)&sA[k * TILE + 64 + ty * 4];
        const float4 b0 = *(const float4*)&sB[k * TILE + tx * 4];
        const float4 b1 = *(const float4*)&sB[k * TILE + 64 + tx * 4];
        const float am[8] = {a0.x, a0.y, a0.z, a0.w, a1.x, a1.y, a1.z, a1.w};
        const float bn[8] = {b0.x, b0.y, b0.z, b0.w, b1.x, b1.y, b1.z, b1.w};
        #pragma unroll
        for (int m = 0; m < 8; ++m)
            #pragma unroll
            for (int n = 0; n < 8; ++n)
                acc[m][n] += am[m] * bn[n];
    }

    // Normal block: rows t = i0 + {ty*4+mm, 64+ty*4+mm}, cols s = j0 + {tx*4.., 64+tx*4..}
    #pragma unroll
    for (int m = 0; m < 8; ++m) {
        const int tl = (m < 4) ? (ty * 4 + m) : (64 + ty * 4 + (m - 4));
        float* row = out + ((size_t)bh * TT + i0 + tl) * TT + j0;
        *(float4*)(row + tx * 4)      = make_float4(acc[m][0], acc[m][1], acc[m][2], acc[m][3]);
        *(float4*)(row + 64 + tx * 4) = make_float4(acc[m][4], acc[m][5], acc[m][6], acc[m][7]);
    }

    // Mirror block (skew symmetry): W[s,t] = -W[t,s]
    if (i != j) {
        #pragma unroll
        for (int n = 0; n < 8; ++n) {
            const int sl = (n < 4) ? (tx * 4 + n) : (64 + tx * 4 + (n - 4));
            float* row = out + ((size_t)bh * TT + j0 + sl) * TT + i0;
            *(float4*)(row + ty * 4)      = make_float4(-acc[0][n], -acc[1][n], -acc[2][n], -acc[3][n]);
            *(float4*)(row + 64 + ty * 4) = make_float4(-acc[4][n], -acc[5][n], -acc[6][n], -acc[7][n]);
        }
    }
}

// ---------------------------------------------------------------------------
extern "C" void kernel_launch(void* const* d_in, const int* in_sizes, int n_in,
                              void* d_out, int out_size) {
    (void)in_sizes; (void)n_in; (void)out_size;
    const float* x = (const float*)d_in[0];
    const float* A = (const float*)d_in[1];
    // d_in[2] = window_size (unused by the reference body)
    float* out = (float*)d_out;

    prep_kernel<<<dim3(NT, BH), 256>>>(x, A);

    const int smem = 2 * DH * TILE * (int)sizeof(float);  // 64 KB dynamic
    cudaFuncSetAttribute(wedge_kernel,
                         cudaFuncAttributeMaxDynamicSharedMemorySize, smem);
    wedge_kernel<<<dim3(NPAIRS, BH), 256, smem>>>(out);
}

// round 2
// speedup vs baseline: 1.0133x; 1.0133x over previous
#include <cuda_runtime.h>
#include <cstdint>

#define BB   2
#define TT   2048
#define HH   16
#define DH   64
#define DD   1024
#define BH   (BB*HH)
#define TILE 128
#define NT   (TT/TILE)
#define NPAIRS (NT*(NT+1)/2)

typedef unsigned long long ull;

#define FFMA2(d,a,b) asm("fma.rn.f32x2 %0, %1, %2, %3;" : "=l"(d) : "l"(a), "l"(b), "l"(d))

__device__ float g_V [(size_t)BH * TT * DH];
__device__ float g_Sv[(size_t)BH * TT * DH];

union Cvt { ull u; float2 f; };

// ---------------------------------------------------------------------------
// Kernel 1: normalize rows, S = A - A^T (value-duplicated for f32x2),
// Sv = v*S with 4-row groups and paired accumulators.
// grid (NT, BH), block 256 (8 warps x 16 rows).
// ---------------------------------------------------------------------------
__global__ __launch_bounds__(256) void prep_kernel(const float* __restrict__ x,
                                                   const float* __restrict__ A) {
    __shared__ float Sd[DH * DH * 2];      // 32 KB, each S value duplicated
    __shared__ float vsm4[8][DH][4];       // 8 KB, per-warp 4-row transposed v

    const int bh = blockIdx.y;
    const int b  = bh / HH;
    const int h  = bh % HH;
    const int tid = threadIdx.x;

    for (int idx = tid; idx < DH * DH; idx += 256) {
        const int d = idx >> 6, e = idx & 63;
        const float s = A[(size_t)h * DH * DH + idx] - A[(size_t)h * DH * DH + e * DH + d];
        *(float2*)&Sd[idx * 2] = make_float2(s, s);
    }
    __syncthreads();

    const int warp = tid >> 5;
    const int lane = tid & 31;
    const int t0   = blockIdx.x * 128 + warp * 16;

    for (int g = 0; g < 4; ++g) {
        const int tb = t0 + g * 4;
        float v0[4], v1[4];
        #pragma unroll
        for (int r = 0; r < 4; ++r) {
            const float* xp = x + ((size_t)(b * TT + tb + r)) * DD + h * DH;
            v0[r] = xp[lane];
            v1[r] = xp[lane + 32];
        }
        #pragma unroll
        for (int r = 0; r < 4; ++r) {
            float ss = v0[r] * v0[r] + v1[r] * v1[r];
            #pragma unroll
            for (int o = 16; o; o >>= 1) ss += __shfl_xor_sync(0xffffffffu, ss, o);
            const float sc = 1.0f / fmaxf(sqrtf(ss), 1e-12f);
            v0[r] *= sc; v1[r] *= sc;
        }
        *(float4*)&vsm4[warp][lane][0]      = make_float4(v0[0], v0[1], v0[2], v0[3]);
        *(float4*)&vsm4[warp][lane + 32][0] = make_float4(v1[0], v1[1], v1[2], v1[3]);
        __syncwarp();

        #pragma unroll
        for (int r = 0; r < 4; ++r) {
            const size_t base = ((size_t)bh * TT + tb + r) * DH;
            g_V[base + lane]      = v0[r];
            g_V[base + lane + 32] = v1[r];
        }

        // Sv matvec: acc pairs = (row 2p, row 2p+1) at col lane / lane+32
        ull a00 = 0, a01 = 0, a10 = 0, a11 = 0;
        #pragma unroll 8
        for (int d = 0; d < DH; ++d) {
            const ulonglong2 a = *(const ulonglong2*)&vsm4[warp][d][0];
            const ull blo = *(const ull*)&Sd[(d * DH + lane) * 2];
            const ull bhi = *(const ull*)&Sd[(d * DH + lane + 32) * 2];
            FFMA2(a00, a.x, blo);
            FFMA2(a01, a.x, bhi);
            FFMA2(a10, a.y, blo);
            FFMA2(a11, a.y, bhi);
        }
        Cvt c00, c01, c10, c11;
        c00.u = a00; c01.u = a01; c10.u = a10; c11.u = a11;
        {
            const size_t b0 = ((size_t)bh * TT + tb + 0) * DH;
            const size_t b1 = ((size_t)bh * TT + tb + 1) * DH;
            const size_t b2 = ((size_t)bh * TT + tb + 2) * DH;
            const size_t b3 = ((size_t)bh * TT + tb + 3) * DH;
            g_Sv[b0 + lane] = c00.f.x;  g_Sv[b0 + lane + 32] = c01.f.x;
            g_Sv[b1 + lane] = c00.f.y;  g_Sv[b1 + lane + 32] = c01.f.y;
            g_Sv[b2 + lane] = c10.f.x;  g_Sv[b2 + lane + 32] = c11.f.x;
            g_Sv[b3 + lane] = c10.f.y;  g_Sv[b3 + lane + 32] = c11.f.y;
        }
        __syncwarp();
    }
}

// ---------------------------------------------------------------------------
// Kernel 2: W = Sv . V^T per (b,h), upper-tri tiles + skew mirror.
// f32x2 inner product: A (Sv) tile stored value-duplicated, B (V) paired.
// grid (NPAIRS, BH), block 256, 8x8 micro-tile (as 8x4 f32x2 accs).
// ---------------------------------------------------------------------------
__global__ __launch_bounds__(256, 2) void wedge_kernel(float* __restrict__ out) {
    extern __shared__ float sm[];
    float* sA2 = sm;                     // [64][128] x2 dup = 64 KB
    float* sB  = sm + DH * TILE * 2;     // [64][128]        = 32 KB

    const int bh = blockIdx.y;

    int p = blockIdx.x;
    int i = 0;
    while (p >= NT - i) { p -= NT - i; ++i; }
    const int j  = i + p;
    const int i0 = i * TILE;
    const int j0 = j * TILE;

    const int tid = threadIdx.x;
    const float* Sv = g_Sv + (size_t)bh * TT * DH;
    const float* V  = g_V  + (size_t)bh * TT * DH;

    #pragma unroll
    for (int s = 0; s < 8; ++s) {
        const int f  = tid + s * 256;
        const int k4 = f >> 7;
        const int t  = f & 127;
        const float4 a = *(const float4*)(Sv + (size_t)(i0 + t) * DH + k4 * 4);
        const float4 b = *(const float4*)(V  + (size_t)(j0 + t) * DH + k4 * 4);
        const int k = k4 * 4;
        *(float2*)&sA2[((k + 0) * TILE + t) * 2] = make_float2(a.x, a.x);
        *(float2*)&sA2[((k + 1) * TILE + t) * 2] = make_float2(a.y, a.y);
        *(float2*)&sA2[((k + 2) * TILE + t) * 2] = make_float2(a.z, a.z);
        *(float2*)&sA2[((k + 3) * TILE + t) * 2] = make_float2(a.w, a.w);
        sB[(k + 0) * TILE + t] = b.x;
        sB[(k + 1) * TILE + t] = b.y;
        sB[(k + 2) * TILE + t] = b.z;
        sB[(k + 3) * TILE + t] = b.w;
    }
    __syncthreads();

    const int tx = tid & 15;   // n direction (s)
    const int ty = tid >> 4;   // m direction (t)

    ull acc[8][4];
    #pragma unroll
    for (int m = 0; m < 8; ++m)
        #pragma unroll
        for (int q = 0; q < 4; ++q) acc[m][q] = 0ull;

    #pragma unroll 8
    for (int k = 0; k < DH; ++k) {
        const ulonglong2 a01 = *(const ulonglong2*)&sA2[(k * TILE + ty * 4) * 2];
        const ulonglong2 a23 = *(const ulonglong2*)&sA2[(k * TILE + ty * 4) * 2 + 4];
        const ulonglong2 a45 = *(const ulonglong2*)&sA2[(k * TILE + 64 + ty * 4) * 2];
        const ulonglong2 a67 = *(const ulonglong2*)&sA2[(k * TILE + 64 + ty * 4) * 2 + 4];
        const ulonglong2 b03 = *(const ulonglong2*)&sB[k * TILE + tx * 4];
        const ulonglong2 b47 = *(const ulonglong2*)&sB[k * TILE + 64 + tx * 4];
        const ull am[8]  = {a01.x, a01.y, a23.x, a23.y, a45.x, a45.y, a67.x, a67.y};
        const ull bn2[4] = {b03.x, b03.y, b47.x, b47.y};
        #pragma unroll
        for (int m = 0; m < 8; ++m) {
            FFMA2(acc[m][0], am[m], bn2[0]);
            FFMA2(acc[m][1], am[m], bn2[1]);
            FFMA2(acc[m][2], am[m], bn2[2]);
            FFMA2(acc[m][3], am[m], bn2[3]);
        }
    }

    // Unpack to scalar view: un[m][n], n ordered cols {tx4+0..3, 64+tx4+0..3}
    float un[8][8];
    #pragma unroll
    for (int m = 0; m < 8; ++m)
        #pragma unroll
        for (int q = 0; q < 4; ++q) {
            Cvt c; c.u = acc[m][q];
            un[m][2 * q]     = c.f.x;
            un[m][2 * q + 1] = c.f.y;
        }

    // Normal tile
    #pragma unroll
    for (int m = 0; m < 8; ++m) {
        const int tl = (m < 4) ? (ty * 4 + m) : (64 + ty * 4 + (m - 4));
        float* row = out + ((size_t)bh * TT + i0 + tl) * TT + j0;
        *(float4*)(row + tx * 4)      = make_float4(un[m][0], un[m][1], un[m][2], un[m][3]);
        *(float4*)(row + 64 + tx * 4) = make_float4(un[m][4], un[m][5], un[m][6], un[m][7]);
    }

    // Mirror tile: W[s,t] = -W[t,s]
    if (i != j) {
        #pragma unroll
        for (int n = 0; n < 8; ++n) {
            const int sl = (n < 4) ? (tx * 4 + n) : (64 + tx * 4 + (n - 4));
            float* row = out + ((size_t)bh * TT + j0 + sl) * TT + i0;
            *(float4*)(row + ty * 4)      = make_float4(-un[0][n], -un[1][n], -un[2][n], -un[3][n]);
            *(float4*)(row + 64 + ty * 4) = make_float4(-un[4][n], -un[5][n], -un[6][n], -un[7][n]);
        }
    }
}

// ---------------------------------------------------------------------------
extern "C" void kernel_launch(void* const* d_in, const int* in_sizes, int n_in,
                              void* d_out, int out_size) {
    (void)in_sizes; (void)n_in; (void)out_size;
    const float* x = (const float*)d_in[0];
    const float* A = (const float*)d_in[1];
    float* out = (float*)d_out;

    prep_kernel<<<dim3(NT, BH), 256>>>(x, A);

    const int smem = 3 * DH * TILE * (int)sizeof(float);  // 96 KB dynamic
    cudaFuncSetAttribute(wedge_kernel,
                         cudaFuncAttributeMaxDynamicSharedMemorySize, smem);
    wedge_kernel<<<dim3(NPAIRS, BH), 256, smem>>>(out);
}

// round 4
// speedup vs baseline: 1.6879x; 1.6658x over previous
#include <cuda_runtime.h>
#include <cuda_bf16.h>
#include <cstdint>

#define BB   2
#define TT   2048
#define HH   16
#define DH   64
#define DD   1024
#define BH   (BB*HH)
#define TILE 128
#define NT   (TT/TILE)
#define NPAIRS (NT*(NT+1)/2)

typedef unsigned long long ull;

#define FFMA2(d,a,b) asm("fma.rn.f32x2 %0, %1, %2, %3;" : "=l"(d) : "l"(a), "l"(b), "l"(d))

__device__ float g_V [(size_t)BH * TT * DH];
__device__ float g_Sv[(size_t)BH * TT * DH];

union Cvt { ull u; float2 f; };

// ============================================================================
// Kernel 1: normalize rows, S = A - A^T, Sv = v*S  (unchanged, proven)
// ============================================================================
__global__ __launch_bounds__(256) void prep_kernel(const float* __restrict__ x,
                                                   const float* __restrict__ A) {
    __shared__ float Sd[DH * DH * 2];
    __shared__ float vsm4[8][DH][4];

    const int bh = blockIdx.y;
    const int b  = bh / HH;
    const int h  = bh % HH;
    const int tid = threadIdx.x;

    for (int idx = tid; idx < DH * DH; idx += 256) {
        const int d = idx >> 6, e = idx & 63;
        const float s = A[(size_t)h * DH * DH + idx] - A[(size_t)h * DH * DH + e * DH + d];
        *(float2*)&Sd[idx * 2] = make_float2(s, s);
    }
    __syncthreads();

    const int warp = tid >> 5;
    const int lane = tid & 31;
    const int t0   = blockIdx.x * 128 + warp * 16;

    for (int g = 0; g < 4; ++g) {
        const int tb = t0 + g * 4;
        float v0[4], v1[4];
        #pragma unroll
        for (int r = 0; r < 4; ++r) {
            const float* xp = x + ((size_t)(b * TT + tb + r)) * DD + h * DH;
            v0[r] = xp[lane];
            v1[r] = xp[lane + 32];
        }
        #pragma unroll
        for (int r = 0; r < 4; ++r) {
            float ss = v0[r] * v0[r] + v1[r] * v1[r];
            #pragma unroll
            for (int o = 16; o; o >>= 1) ss += __shfl_xor_sync(0xffffffffu, ss, o);
            const float sc = 1.0f / fmaxf(sqrtf(ss), 1e-12f);
            v0[r] *= sc; v1[r] *= sc;
        }
        *(float4*)&vsm4[warp][lane][0]      = make_float4(v0[0], v0[1], v0[2], v0[3]);
        *(float4*)&vsm4[warp][lane + 32][0] = make_float4(v1[0], v1[1], v1[2], v1[3]);
        __syncwarp();

        #pragma unroll
        for (int r = 0; r < 4; ++r) {
            const size_t base = ((size_t)bh * TT + tb + r) * DH;
            g_V[base + lane]      = v0[r];
            g_V[base + lane + 32] = v1[r];
        }

        ull a00 = 0, a01 = 0, a10 = 0, a11 = 0;
        #pragma unroll 8
        for (int d = 0; d < DH; ++d) {
            const ulonglong2 a = *(const ulonglong2*)&vsm4[warp][d][0];
            const ull blo = *(const ull*)&Sd[(d * DH + lane) * 2];
            const ull bhi = *(const ull*)&Sd[(d * DH + lane + 32) * 2];
            FFMA2(a00, a.x, blo);
            FFMA2(a01, a.x, bhi);
            FFMA2(a10, a.y, blo);
            FFMA2(a11, a.y, bhi);
        }
        Cvt c00, c01, c10, c11;
        c00.u = a00; c01.u = a01; c10.u = a10; c11.u = a11;
        {
            const size_t b0 = ((size_t)bh * TT + tb + 0) * DH;
            const size_t b1 = ((size_t)bh * TT + tb + 1) * DH;
            const size_t b2 = ((size_t)bh * TT + tb + 2) * DH;
            const size_t b3 = ((size_t)bh * TT + tb + 3) * DH;
            g_Sv[b0 + lane] = c00.f.x;  g_Sv[b0 + lane + 32] = c01.f.x;
            g_Sv[b1 + lane] = c00.f.y;  g_Sv[b1 + lane + 32] = c01.f.y;
            g_Sv[b2 + lane] = c10.f.x;  g_Sv[b2 + lane + 32] = c11.f.x;
            g_Sv[b3 + lane] = c10.f.y;  g_Sv[b3 + lane + 32] = c11.f.y;
        }
        __syncwarp();
    }
}

// ============================================================================
// Kernel 2: bf16 mma.sync wedge with 3-pass fp32 compensation.
// grid (NPAIRS, BH), 256 threads (8 warps), 2 CTAs/SM.
// Warp w computes rows 16w..16w+15 of the 128x128 tile, full 128 cols.
// ============================================================================
#define LDB    144                       // bytes per smem tile row (64 bf16 + pad)
#define T_AH   0
#define T_AL   (128*LDB)
#define T_BH   (2*128*LDB)
#define T_BL   (3*128*LDB)
#define STG_STRIDE 20                    // floats, 16B-aligned row stride
#define SMEM_WEDGE 81920                 // max(4*128*144, 8*128*20*4)

__device__ __forceinline__ uint32_t smem_u32(const void* p) {
    uint32_t a;
    asm("{ .reg .u64 t; cvta.to.shared.u64 t, %1; cvt.u32.u64 %0, t; }"
        : "=r"(a) : "l"(p));
    return a;
}

#define LDSM4(r, addr) \
    asm volatile("ldmatrix.sync.aligned.m8n8.x4.shared.b16 {%0,%1,%2,%3}, [%4];" \
        : "=r"((r)[0]), "=r"((r)[1]), "=r"((r)[2]), "=r"((r)[3]) : "r"(addr))

#define MMA16816(d, a, b0, b1) \
    asm volatile("mma.sync.aligned.m16n8k16.row.col.f32.bf16.bf16.f32 " \
        "{%0,%1,%2,%3},{%4,%5,%6,%7},{%8,%9},{%0,%1,%2,%3};" \
        : "+f"((d)[0]), "+f"((d)[1]), "+f"((d)[2]), "+f"((d)[3]) \
        : "r"((a)[0]), "r"((a)[1]), "r"((a)[2]), "r"((a)[3]), "r"(b0), "r"(b1))

__device__ __forceinline__ void split2(float x, float y, uint32_t& hi, uint32_t& lo) {
    const __nv_bfloat16 hx = __float2bfloat16_rn(x);
    const __nv_bfloat16 hy = __float2bfloat16_rn(y);
    const __nv_bfloat162 h2 = __nv_bfloat162(hx, hy);
    hi = *(const uint32_t*)&h2;
    const __nv_bfloat162 l2 = __floats2bfloat162_rn(x - __bfloat162float(hx),
                                                    y - __bfloat162float(hy));
    lo = *(const uint32_t*)&l2;
}

// split a 128x64 f32 tile into bf16 hi/lo smem images (row-major, LDB pad)
__device__ __forceinline__ void load_split(const float* __restrict__ src,
                                           char* hi, char* lo, int tid) {
    #pragma unroll
    for (int p = 0; p < 8; ++p) {
        const int f   = p * 256 + tid;      // float4 index, 0..2047
        const int row = f >> 4;
        const int c4  = f & 15;
        const float4 v = ((const float4*)src)[row * 16 + c4];
        uint2 h, l;
        split2(v.x, v.y, h.x, l.x);
        split2(v.z, v.w, h.y, l.y);
        const int off = row * LDB + c4 * 8;
        *(uint2*)(hi + off) = h;
        *(uint2*)(lo + off) = l;
    }
}

__global__ __launch_bounds__(256, 2) void wedge_mma(float* __restrict__ out) {
    extern __shared__ char sm[];
    const uint32_t sb = smem_u32(sm);
    const int tid  = threadIdx.x;
    const int w    = tid >> 5;
    const int lane = tid & 31;
    const int bh   = blockIdx.y;

    int p = blockIdx.x;
    int i = 0;
    while (p >= NT - i) { p -= NT - i; ++i; }
    const int j  = i + p;
    const int i0 = i * TILE;
    const int j0 = j * TILE;

    const float* Sv = g_Sv + (size_t)bh * TT * DH;
    const float* V  = g_V  + (size_t)bh * TT * DH;
    float* outb = out + (size_t)bh * TT * TT;

    load_split(Sv + (size_t)i0 * DH, sm + T_AH, sm + T_AL, tid);
    load_split(V  + (size_t)j0 * DH, sm + T_BH, sm + T_BL, tid);
    __syncthreads();

    // ldmatrix base addresses
    const uint32_t aRow  = (uint32_t)(16 * w + (lane & 15));
    const uint32_t aOffs = aRow * LDB + ((uint32_t)(lane >> 4)) * 16;
    const uint32_t aH = sb + T_AH + aOffs;
    const uint32_t aL = sb + T_AL + aOffs;
    const uint32_t bn   = (uint32_t)((lane & 7) | ((lane >> 1) & 8));   // n 0..15
    const uint32_t bOff = bn * LDB + ((uint32_t)(lane & 8)) * 2;        // + k8 sel
    const uint32_t bHb = sb + T_BH + bOff;
    const uint32_t bLb = sb + T_BL + bOff;

    float acc[16][4];
    #pragma unroll
    for (int n = 0; n < 16; ++n)
        #pragma unroll
        for (int q = 0; q < 4; ++q) acc[n][q] = 0.f;

    #pragma unroll
    for (int kk = 0; kk < 4; ++kk) {
        uint32_t ah[4], al[4];
        LDSM4(ah, aH + kk * 32);
        LDSM4(al, aL + kk * 32);
        #pragma unroll
        for (int nt2 = 0; nt2 < 8; ++nt2) {
            uint32_t bhf[4], blf[4];
            const uint32_t boff = (uint32_t)(nt2 * 16 * LDB + kk * 32);
            LDSM4(bhf, bHb + boff);
            LDSM4(blf, bLb + boff);
            MMA16816(acc[2 * nt2],     ah, bhf[0], bhf[1]);
            MMA16816(acc[2 * nt2 + 1], ah, bhf[2], bhf[3]);
            MMA16816(acc[2 * nt2],     ah, blf[0], blf[1]);
            MMA16816(acc[2 * nt2 + 1], ah, blf[2], blf[3]);
            MMA16816(acc[2 * nt2],     al, bhf[0], bhf[1]);
            MMA16816(acc[2 * nt2 + 1], al, bhf[2], bhf[3]);
        }
    }

    // ---- direct store of tile (i,j) ----
    {
        const int r0 = i0 + 16 * w + (lane >> 2);
        const int c0 = j0 + (lane & 3) * 2;
        #pragma unroll
        for (int nt = 0; nt < 16; ++nt) {
            *(float2*)&outb[(size_t)r0 * TT + c0 + nt * 8]       = make_float2(acc[nt][0], acc[nt][1]);
            *(float2*)&outb[(size_t)(r0 + 8) * TT + c0 + nt * 8] = make_float2(acc[nt][2], acc[nt][3]);
        }
    }

    // ---- mirror tile (j,i) = -transpose, via per-warp smem stage ----
    if (i != j) {
        __syncthreads();   // everyone done reading bf16 tiles; reuse smem
        float* stg = (float*)sm + w * (128 * STG_STRIDE);
        const int rl = lane >> 2;              // local t row 0..7
        #pragma unroll
        for (int nt = 0; nt < 16; ++nt) {
            const int c0 = nt * 8 + (lane & 3) * 2;
            stg[(c0    ) * STG_STRIDE + rl]     = -acc[nt][0];
            stg[(c0 + 1) * STG_STRIDE + rl]     = -acc[nt][1];
            stg[(c0    ) * STG_STRIDE + rl + 8] = -acc[nt][2];
            stg[(c0 + 1) * STG_STRIDE + rl + 8] = -acc[nt][3];
        }
        __syncwarp();
        const int tcol = i0 + 16 * w + (lane & 3) * 4;
        #pragma unroll
        for (int pp = 0; pp < 16; ++pp) {
            const int s = pp * 8 + (lane >> 2);
            const float4 v = *(const float4*)&stg[s * STG_STRIDE + (lane & 3) * 4];
            *(float4*)&outb[(size_t)(j0 + s) * TT + tcol] = v;
        }
    }
}

// ============================================================================
extern "C" void kernel_launch(void* const* d_in, const int* in_sizes, int n_in,
                              void* d_out, int out_size) {
    (void)in_sizes; (void)n_in; (void)out_size;
    const float* x = (const float*)d_in[0];
    const float* A = (const float*)d_in[1];
    float* out = (float*)d_out;

    prep_kernel<<<dim3(NT, BH), 256>>>(x, A);

    cudaFuncSetAttribute(wedge_mma, cudaFuncAttributeMaxDynamicSharedMemorySize, SMEM_WEDGE);
    wedge_mma<<<dim3(NPAIRS, BH), 256, SMEM_WEDGE>>>(out);
}

// round 5
// speedup vs baseline: 1.7972x; 1.0647x over previous
#include <cuda_runtime.h>
#include <cuda_bf16.h>
#include <cstdint>

#define BB   2
#define TT   2048
#define HH   16
#define DH   64
#define DD   1024
#define BH   (BB*HH)
#define TILE 128
#define NT   (TT/TILE)
#define NPAIRS (NT*(NT+1)/2)

__device__ float g_V [(size_t)BH * TT * DH];
__device__ float g_Sv[(size_t)BH * TT * DH];

// ============================================================================
// Kernel 1: normalize rows, S = A - A^T (scalar), Sv = v*S.
// Lane owns cols (2*lane, 2*lane+1). grid (NT, BH), block 256.
// ============================================================================
__global__ __launch_bounds__(256) void prep_kernel(const float* __restrict__ x,
                                                   const float* __restrict__ A) {
    __shared__ float S[DH * DH];          // 16 KB
    __shared__ float vsm[8][DH][4];       // [warp][d][r], 8 KB

    const int bh = blockIdx.y;
    const int b  = bh / HH;
    const int h  = bh % HH;
    const int tid = threadIdx.x;

    for (int idx = tid; idx < DH * DH; idx += 256) {
        const int d = idx >> 6, e = idx & 63;
        S[idx] = A[(size_t)h * DH * DH + idx] - A[(size_t)h * DH * DH + e * DH + d];
    }
    __syncthreads();

    const int warp = tid >> 5;
    const int lane = tid & 31;
    const int t0   = blockIdx.x * 128 + warp * 16;

    for (int g = 0; g < 4; ++g) {
        const int tb = t0 + g * 4;
        float2 v[4];
        #pragma unroll
        for (int r = 0; r < 4; ++r)
            v[r] = *(const float2*)(x + ((size_t)(b * TT + tb + r)) * DD + h * DH + lane * 2);
        #pragma unroll
        for (int r = 0; r < 4; ++r) {
            float ss = v[r].x * v[r].x + v[r].y * v[r].y;
            #pragma unroll
            for (int o = 16; o; o >>= 1) ss += __shfl_xor_sync(0xffffffffu, ss, o);
            const float sc = 1.0f / fmaxf(sqrtf(ss), 1e-12f);
            v[r].x *= sc; v[r].y *= sc;
        }
        *(float4*)&vsm[warp][2 * lane][0]     = make_float4(v[0].x, v[1].x, v[2].x, v[3].x);
        *(float4*)&vsm[warp][2 * lane + 1][0] = make_float4(v[0].y, v[1].y, v[2].y, v[3].y);
        __syncwarp();

        float2 acc[4];
        #pragma unroll
        for (int r = 0; r < 4; ++r) acc[r] = make_float2(0.f, 0.f);
        #pragma unroll 8
        for (int d = 0; d < DH; ++d) {
            const float4 vr = *(const float4*)&vsm[warp][d][0];
            const float2 sc2 = *(const float2*)&S[d * DH + lane * 2];
            acc[0].x += vr.x * sc2.x;  acc[0].y += vr.x * sc2.y;
            acc[1].x += vr.y * sc2.x;  acc[1].y += vr.y * sc2.y;
            acc[2].x += vr.z * sc2.x;  acc[2].y += vr.z * sc2.y;
            acc[3].x += vr.w * sc2.x;  acc[3].y += vr.w * sc2.y;
        }
        #pragma unroll
        for (int r = 0; r < 4; ++r) {
            const size_t base = ((size_t)bh * TT + tb + r) * DH + lane * 2;
            *(float2*)&g_V [base] = v[r];
            *(float2*)&g_Sv[base] = acc[r];
        }
        __syncwarp();
    }
}

// ============================================================================
// Kernel 2: bf16 mma.sync wedge, 3-pass compensation, 2x4 warp tiling,
// fully-coalesced staged epilogue. grid (NPAIRS, BH), 256 threads, 2 CTA/SM.
// ============================================================================
#define LDB    144                       // bytes per smem bf16 tile row
#define T_AH   0
#define T_AL   (128*LDB)
#define T_BH   (2*128*LDB)
#define T_BL   (3*128*LDB)
#define STGS   136                       // stage row stride in floats
#define SMEM_WEDGE (4*128*LDB)           // 73728 >= 128*136*4 stage

__device__ __forceinline__ uint32_t smem_u32(const void* p) {
    uint32_t a;
    asm("{ .reg .u64 t; cvta.to.shared.u64 t, %1; cvt.u32.u64 %0, t; }"
        : "=r"(a) : "l"(p));
    return a;
}

#define LDSM4(r, addr) \
    asm volatile("ldmatrix.sync.aligned.m8n8.x4.shared.b16 {%0,%1,%2,%3}, [%4];" \
        : "=r"((r)[0]), "=r"((r)[1]), "=r"((r)[2]), "=r"((r)[3]) : "r"(addr))

#define MMA16816(d, a, b0, b1) \
    asm volatile("mma.sync.aligned.m16n8k16.row.col.f32.bf16.bf16.f32 " \
        "{%0,%1,%2,%3},{%4,%5,%6,%7},{%8,%9},{%0,%1,%2,%3};" \
        : "+f"((d)[0]), "+f"((d)[1]), "+f"((d)[2]), "+f"((d)[3]) \
        : "r"((a)[0]), "r"((a)[1]), "r"((a)[2]), "r"((a)[3]), "r"(b0), "r"(b1))

__device__ __forceinline__ void split2(float x, float y, uint32_t& hi, uint32_t& lo) {
    const __nv_bfloat16 hx = __float2bfloat16_rn(x);
    const __nv_bfloat16 hy = __float2bfloat16_rn(y);
    const __nv_bfloat162 h2 = __nv_bfloat162(hx, hy);
    hi = *(const uint32_t*)&h2;
    const __nv_bfloat162 l2 = __floats2bfloat162_rn(x - __bfloat162float(hx),
                                                    y - __bfloat162float(hy));
    lo = *(const uint32_t*)&l2;
}

__device__ __forceinline__ void load_split(const float* __restrict__ src,
                                           char* hi, char* lo, int tid) {
    #pragma unroll
    for (int p = 0; p < 8; ++p) {
        const int f   = p * 256 + tid;
        const int row = f >> 4;
        const int c4  = f & 15;
        const float4 v = ((const float4*)src)[row * 16 + c4];
        uint2 h, l;
        split2(v.x, v.y, h.x, l.x);
        split2(v.z, v.w, h.y, l.y);
        const int off = row * LDB + c4 * 8;
        *(uint2*)(hi + off) = h;
        *(uint2*)(lo + off) = l;
    }
}

__global__ __launch_bounds__(256, 2) void wedge_mma(float* __restrict__ out) {
    extern __shared__ char sm[];
    const uint32_t sb = smem_u32(sm);
    const int tid  = threadIdx.x;
    const int w    = tid >> 5;
    const int lane = tid & 31;
    const int bh   = blockIdx.y;
    const int wm   = w >> 2;     // 0..1 (m direction)
    const int wn   = w & 3;      // 0..3 (n direction)

    int p = blockIdx.x;
    int i = 0;
    while (p >= NT - i) { p -= NT - i; ++i; }
    const int j  = i + p;
    const int i0 = i * TILE;
    const int j0 = j * TILE;

    const float* Sv = g_Sv + (size_t)bh * TT * DH;
    const float* V  = g_V  + (size_t)bh * TT * DH;
    float* outb = out + (size_t)bh * TT * TT;

    load_split(Sv + (size_t)i0 * DH, sm + T_AH, sm + T_AL, tid);
    load_split(V  + (size_t)j0 * DH, sm + T_BH, sm + T_BL, tid);
    __syncthreads();

    // ldmatrix bases
    const uint32_t aB = sb + T_AH + (uint32_t)(wm * 64 + (lane & 15)) * LDB
                      + ((uint32_t)(lane >> 4)) * 16;
    const uint32_t bn = (uint32_t)((lane & 7) | ((lane >> 1) & 8));
    const uint32_t bB = sb + T_BH + ((uint32_t)(wn * 32) + bn) * LDB
                      + ((uint32_t)(lane & 8)) * 2;

    float acc[4][4][4];
    #pragma unroll
    for (int mt = 0; mt < 4; ++mt)
        #pragma unroll
        for (int nt = 0; nt < 4; ++nt)
            #pragma unroll
            for (int q = 0; q < 4; ++q) acc[mt][nt][q] = 0.f;

    #pragma unroll
    for (int kk = 0; kk < 4; ++kk) {
        uint32_t bh0[4], bl0[4], bh1[4], bl1[4];
        LDSM4(bh0, bB + kk * 32);
        LDSM4(bl0, bB + (T_BL - T_BH) + kk * 32);
        LDSM4(bh1, bB + 16 * LDB + kk * 32);
        LDSM4(bl1, bB + (T_BL - T_BH) + 16 * LDB + kk * 32);
        #pragma unroll
        for (int mt = 0; mt < 4; ++mt) {
            uint32_t ah[4], al[4];
            LDSM4(ah, aB + mt * 16 * LDB + kk * 32);
            LDSM4(al, aB + (T_AL - T_AH) + mt * 16 * LDB + kk * 32);
            MMA16816(acc[mt][0], ah, bh0[0], bh0[1]);
            MMA16816(acc[mt][1], ah, bh0[2], bh0[3]);
            MMA16816(acc[mt][2], ah, bh1[0], bh1[1]);
            MMA16816(acc[mt][3], ah, bh1[2], bh1[3]);
            MMA16816(acc[mt][0], ah, bl0[0], bl0[1]);
            MMA16816(acc[mt][1], ah, bl0[2], bl0[3]);
            MMA16816(acc[mt][2], ah, bl1[0], bl1[1]);
            MMA16816(acc[mt][3], ah, bl1[2], bl1[3]);
            MMA16816(acc[mt][0], al, bh0[0], bh0[1]);
            MMA16816(acc[mt][1], al, bh0[2], bh0[3]);
            MMA16816(acc[mt][2], al, bh1[0], bh1[1]);
            MMA16816(acc[mt][3], al, bh1[2], bh1[3]);
        }
    }

    float* stg = (float*)sm;
    const int rql = lane >> 2;
    const int cql = (lane & 3) * 2;

    // ---- tile (i,j): stage row-major then stream coalesced ----
    __syncthreads();
    #pragma unroll
    for (int mt = 0; mt < 4; ++mt)
        #pragma unroll
        for (int nt = 0; nt < 4; ++nt) {
            const int row = wm * 64 + mt * 16 + rql;
            const int col = wn * 32 + nt * 8 + cql;
            *(float2*)&stg[row * STGS + col]       = make_float2(acc[mt][nt][0], acc[mt][nt][1]);
            *(float2*)&stg[(row + 8) * STGS + col] = make_float2(acc[mt][nt][2], acc[mt][nt][3]);
        }
    __syncthreads();
    #pragma unroll
    for (int r8 = 0; r8 < 16; ++r8) {
        const int row = r8 * 8 + w;
        const float4 v = *(const float4*)&stg[row * STGS + lane * 4];
        *(float4*)&outb[(size_t)(i0 + row) * TT + j0 + lane * 4] = v;
    }

    // ---- tile (j,i) = -transpose ----
    if (i != j) {
        __syncthreads();
        #pragma unroll
        for (int mt = 0; mt < 4; ++mt)
            #pragma unroll
            for (int nt = 0; nt < 4; ++nt) {
                const int row = wm * 64 + mt * 16 + rql;
                const int col = wn * 32 + nt * 8 + cql;
                stg[col * STGS + row]           = -acc[mt][nt][0];
                stg[(col + 1) * STGS + row]     = -acc[mt][nt][1];
                stg[col * STGS + row + 8]       = -acc[mt][nt][2];
                stg[(col + 1) * STGS + row + 8] = -acc[mt][nt][3];
            }
        __syncthreads();
        #pragma unroll
        for (int r8 = 0; r8 < 16; ++r8) {
            const int srow = r8 * 8 + w;
            const float4 v = *(const float4*)&stg[srow * STGS + lane * 4];
            *(float4*)&outb[(size_t)(j0 + srow) * TT + i0 + lane * 4] = v;
        }
    }
}

// ============================================================================
extern "C" void kernel_launch(void* const* d_in, const int* in_sizes, int n_in,
                              void* d_out, int out_size) {
    (void)in_sizes; (void)n_in; (void)out_size;
    const float* x = (const float*)d_in[0];
    const float* A = (const float*)d_in[1];
    float* out = (float*)d_out;

    prep_kernel<<<dim3(NT, BH), 256>>>(x, A);

    cudaFuncSetAttribute(wedge_mma, cudaFuncAttributeMaxDynamicSharedMemorySize, SMEM_WEDGE);
    wedge_mma<<<dim3(NPAIRS, BH), 256, SMEM_WEDGE>>>(out);
}

// round 6
// speedup vs baseline: 2.2075x; 1.2283x over previous
#include <cuda_runtime.h>
#include <cuda_fp16.h>
#include <cstdint>

#define BB   2
#define TT   2048
#define HH   16
#define DH   64
#define DD   1024
#define BH   (BB*HH)
#define TILE 128
#define NT   (TT/TILE)
#define NPAIRS (NT*(NT+1)/2)

__device__ float g_V [(size_t)BH * TT * DH];
__device__ float g_Sv[(size_t)BH * TT * DH];

// ============================================================================
// Kernel 1: normalize rows, S = A - A^T, Sv = v*S (unchanged from round 5)
// ============================================================================
__global__ __launch_bounds__(256) void prep_kernel(const float* __restrict__ x,
                                                   const float* __restrict__ A) {
    __shared__ float S[DH * DH];
    __shared__ float vsm[8][DH][4];

    const int bh = blockIdx.y;
    const int b  = bh / HH;
    const int h  = bh % HH;
    const int tid = threadIdx.x;

    for (int idx = tid; idx < DH * DH; idx += 256) {
        const int d = idx >> 6, e = idx & 63;
        S[idx] = A[(size_t)h * DH * DH + idx] - A[(size_t)h * DH * DH + e * DH + d];
    }
    __syncthreads();

    const int warp = tid >> 5;
    const int lane = tid & 31;
    const int t0   = blockIdx.x * 128 + warp * 16;

    for (int g = 0; g < 4; ++g) {
        const int tb = t0 + g * 4;
        float2 v[4];
        #pragma unroll
        for (int r = 0; r < 4; ++r)
            v[r] = *(const float2*)(x + ((size_t)(b * TT + tb + r)) * DD + h * DH + lane * 2);
        #pragma unroll
        for (int r = 0; r < 4; ++r) {
            float ss = v[r].x * v[r].x + v[r].y * v[r].y;
            #pragma unroll
            for (int o = 16; o; o >>= 1) ss += __shfl_xor_sync(0xffffffffu, ss, o);
            const float sc = 1.0f / fmaxf(sqrtf(ss), 1e-12f);
            v[r].x *= sc; v[r].y *= sc;
        }
        *(float4*)&vsm[warp][2 * lane][0]     = make_float4(v[0].x, v[1].x, v[2].x, v[3].x);
        *(float4*)&vsm[warp][2 * lane + 1][0] = make_float4(v[0].y, v[1].y, v[2].y, v[3].y);
        __syncwarp();

        float2 acc[4];
        #pragma unroll
        for (int r = 0; r < 4; ++r) acc[r] = make_float2(0.f, 0.f);
        #pragma unroll 8
        for (int d = 0; d < DH; ++d) {
            const float4 vr = *(const float4*)&vsm[warp][d][0];
            const float2 sc2 = *(const float2*)&S[d * DH + lane * 2];
            acc[0].x += vr.x * sc2.x;  acc[0].y += vr.x * sc2.y;
            acc[1].x += vr.y * sc2.x;  acc[1].y += vr.y * sc2.y;
            acc[2].x += vr.z * sc2.x;  acc[2].y += vr.z * sc2.y;
            acc[3].x += vr.w * sc2.x;  acc[3].y += vr.w * sc2.y;
        }
        #pragma unroll
        for (int r = 0; r < 4; ++r) {
            const size_t base = ((size_t)bh * TT + tb + r) * DH + lane * 2;
            *(float2*)&g_V [base] = v[r];
            *(float2*)&g_Sv[base] = acc[r];
        }
        __syncwarp();
    }
}

// ============================================================================
// Kernel 2: fp16 mma.sync wedge, 2-pass compensation (AhBh + AhBl),
// per-warp fully-coalesced epilogue (no CTA barriers after mainloop).
// grid (NPAIRS, BH), 256 threads, 2 CTA/SM.
// ============================================================================
#define LDB    144                       // bytes per smem fp16 tile row
#define T_AH   0
#define T_BH   (128*LDB)                 // 18432
#define T_BL   (2*128*LDB)               // 36864
#define P_STG  (3*128*LDB)               // 55296
#define WSLICE 4608                      // per-warp stage bytes
#define SMEM_WEDGE (P_STG + 8*WSLICE)    // 92160

__device__ __forceinline__ uint32_t smem_u32(const void* p) {
    uint32_t a;
    asm("{ .reg .u64 t; cvta.to.shared.u64 t, %1; cvt.u32.u64 %0, t; }"
        : "=r"(a) : "l"(p));
    return a;
}

#define LDSM4(r, addr) \
    asm volatile("ldmatrix.sync.aligned.m8n8.x4.shared.b16 {%0,%1,%2,%3}, [%4];" \
        : "=r"((r)[0]), "=r"((r)[1]), "=r"((r)[2]), "=r"((r)[3]) : "r"(addr))

#define MMA16816(d, a, b0, b1) \
    asm volatile("mma.sync.aligned.m16n8k16.row.col.f32.f16.f16.f32 " \
        "{%0,%1,%2,%3},{%4,%5,%6,%7},{%8,%9},{%0,%1,%2,%3};" \
        : "+f"((d)[0]), "+f"((d)[1]), "+f"((d)[2]), "+f"((d)[3]) \
        : "r"((a)[0]), "r"((a)[1]), "r"((a)[2]), "r"((a)[3]), "r"(b0), "r"(b1))

__device__ __forceinline__ void split2h(float x, float y, uint32_t& hi, uint32_t& lo) {
    const __half hx = __float2half_rn(x);
    const __half hy = __float2half_rn(y);
    const __half2 h2(hx, hy);
    hi = *(const uint32_t*)&h2;
    const __half2 l2 = __floats2half2_rn(x - __half2float(hx), y - __half2float(hy));
    lo = *(const uint32_t*)&l2;
}

// A tile: hi image only
__device__ __forceinline__ void load_convA(const float* __restrict__ src,
                                           char* hi, int tid) {
    #pragma unroll
    for (int p = 0; p < 8; ++p) {
        const int f   = p * 256 + tid;
        const int row = f >> 4;
        const int c4  = f & 15;
        const float4 v = ((const float4*)src)[row * 16 + c4];
        uint2 h;
        const __half2 h0 = __floats2half2_rn(v.x, v.y);
        const __half2 h1 = __floats2half2_rn(v.z, v.w);
        h.x = *(const uint32_t*)&h0;
        h.y = *(const uint32_t*)&h1;
        *(uint2*)(hi + row * LDB + c4 * 8) = h;
    }
}

// B tile: hi + lo images
__device__ __forceinline__ void load_splitB(const float* __restrict__ src,
                                            char* hi, char* lo, int tid) {
    #pragma unroll
    for (int p = 0; p < 8; ++p) {
        const int f   = p * 256 + tid;
        const int row = f >> 4;
        const int c4  = f & 15;
        const float4 v = ((const float4*)src)[row * 16 + c4];
        uint2 h, l;
        split2h(v.x, v.y, h.x, l.x);
        split2h(v.z, v.w, h.y, l.y);
        const int off = row * LDB + c4 * 8;
        *(uint2*)(hi + off) = h;
        *(uint2*)(lo + off) = l;
    }
}

__global__ __launch_bounds__(256, 2) void wedge_mma(float* __restrict__ out) {
    extern __shared__ char sm[];
    const uint32_t sb = smem_u32(sm);
    const int tid  = threadIdx.x;
    const int w    = tid >> 5;
    const int lane = tid & 31;
    const int bh   = blockIdx.y;
    const int wm   = w >> 2;     // 0..1
    const int wn   = w & 3;      // 0..3

    int p = blockIdx.x;
    int i = 0;
    while (p >= NT - i) { p -= NT - i; ++i; }
    const int j  = i + p;
    const int i0 = i * TILE;
    const int j0 = j * TILE;

    const float* Sv = g_Sv + (size_t)bh * TT * DH;
    const float* V  = g_V  + (size_t)bh * TT * DH;
    float* outb = out + (size_t)bh * TT * TT;

    load_convA (Sv + (size_t)i0 * DH, sm + T_AH, tid);
    load_splitB(V  + (size_t)j0 * DH, sm + T_BH, sm + T_BL, tid);
    __syncthreads();

    const uint32_t aB = sb + T_AH + (uint32_t)(wm * 64 + (lane & 15)) * LDB
                      + ((uint32_t)(lane >> 4)) * 16;
    const uint32_t bn = (uint32_t)((lane & 7) | ((lane >> 1) & 8));
    const uint32_t bB = sb + T_BH + ((uint32_t)(wn * 32) + bn) * LDB
                      + ((uint32_t)(lane & 8)) * 2;

    float acc[4][4][4];
    #pragma unroll
    for (int mt = 0; mt < 4; ++mt)
        #pragma unroll
        for (int nt = 0; nt < 4; ++nt)
            #pragma unroll
            for (int q = 0; q < 4; ++q) acc[mt][nt][q] = 0.f;

    #pragma unroll
    for (int kk = 0; kk < 4; ++kk) {
        uint32_t bh0[4], bh1[4], bl0[4], bl1[4];
        LDSM4(bh0, bB + kk * 32);
        LDSM4(bh1, bB + 16 * LDB + kk * 32);
        LDSM4(bl0, bB + (T_BL - T_BH) + kk * 32);
        LDSM4(bl1, bB + (T_BL - T_BH) + 16 * LDB + kk * 32);
        #pragma unroll
        for (int mt = 0; mt < 4; ++mt) {
            uint32_t ah[4];
            LDSM4(ah, aB + mt * 16 * LDB + kk * 32);
            MMA16816(acc[mt][0], ah, bh0[0], bh0[1]);
            MMA16816(acc[mt][1], ah, bh0[2], bh0[3]);
            MMA16816(acc[mt][2], ah, bh1[0], bh1[1]);
            MMA16816(acc[mt][3], ah, bh1[2], bh1[3]);
            MMA16816(acc[mt][0], ah, bl0[0], bl0[1]);
            MMA16816(acc[mt][1], ah, bl0[2], bl0[3]);
            MMA16816(acc[mt][2], ah, bl1[0], bl1[1]);
            MMA16816(acc[mt][3], ah, bl1[2], bl1[3]);
        }
    }

    // ---- per-warp epilogue: no CTA barriers from here on ----
    float* stg = (float*)(sm + P_STG + w * WSLICE);
    const int rql = lane >> 2;
    const int cql = (lane & 3) * 2;

    // normal tile (i,j): warp block rows [wm*64, +64), cols [wn*32, +32)
    #pragma unroll
    for (int mt = 0; mt < 4; ++mt) {
        #pragma unroll
        for (int nt = 0; nt < 4; ++nt) {
            const int col = nt * 8 + cql;
            *(float2*)&stg[rql * 40 + col]       = make_float2(acc[mt][nt][0], acc[mt][nt][1]);
            *(float2*)&stg[(rql + 8) * 40 + col] = make_float2(acc[mt][nt][2], acc[mt][nt][3]);
        }
        __syncwarp();
        #pragma unroll
        for (int pp = 0; pp < 4; ++pp) {
            const int r = pp * 4 + (lane >> 3);
            const float4 v = *(const float4*)&stg[r * 40 + (lane & 7) * 4];
            const int grow = i0 + wm * 64 + mt * 16 + r;
            *(float4*)&outb[(size_t)grow * TT + j0 + wn * 32 + (lane & 7) * 4] = v;
        }
        __syncwarp();
    }

    // mirror tile (j,i) = -transpose: mirror rows [wn*32, +32), cols [wm*64, +64)
    if (i != j) {
        #pragma unroll
        for (int cc = 0; cc < 2; ++cc) {
            #pragma unroll
            for (int ntl = 0; ntl < 2; ++ntl) {
                const int nt = cc * 2 + ntl;
                const int c0 = ntl * 8 + cql;
                #pragma unroll
                for (int mt = 0; mt < 4; ++mt) {
                    const int rbase = mt * 16 + rql;
                    stg[c0 * 72 + rbase]           = -acc[mt][nt][0];
                    stg[(c0 + 1) * 72 + rbase]     = -acc[mt][nt][1];
                    stg[c0 * 72 + rbase + 8]       = -acc[mt][nt][2];
                    stg[(c0 + 1) * 72 + rbase + 8] = -acc[mt][nt][3];
                }
            }
            __syncwarp();
            #pragma unroll
            for (int pp = 0; pp < 8; ++pp) {
                const int c = pp * 2 + (lane >> 4);
                const float4 v = *(const float4*)&stg[c * 72 + (lane & 15) * 4];
                const int grow = j0 + wn * 32 + cc * 16 + c;
                *(float4*)&outb[(size_t)grow * TT + i0 + wm * 64 + (lane & 15) * 4] = v;
            }
            __syncwarp();
        }
    }
}

// ============================================================================
extern "C" void kernel_launch(void* const* d_in, const int* in_sizes, int n_in,
                              void* d_out, int out_size) {
    (void)in_sizes; (void)n_in; (void)out_size;
    const float* x = (const float*)d_in[0];
    const float* A = (const float*)d_in[1];
    float* out = (float*)d_out;

    prep_kernel<<<dim3(NT, BH), 256>>>(x, A);

    cudaFuncSetAttribute(wedge_mma, cudaFuncAttributeMaxDynamicSharedMemorySize, SMEM_WEDGE);
    wedge_mma<<<dim3(NPAIRS, BH), 256, SMEM_WEDGE>>>(out);
}

// round 7
// speedup vs baseline: 2.5716x; 1.1649x over previous
#include <cuda_runtime.h>
#include <cuda_fp16.h>
#include <cstdint>

#define BB   2
#define TT   2048
#define HH   16
#define DH   64
#define DD   1024
#define BH   (BB*HH)
#define TILE 128
#define NT   (TT/TILE)
#define NPAIRS (NT*(NT+1)/2)

// fp16 scratch (8 MB each, 24 MB total -> L2 resident)
__device__ __half g_Vh [(size_t)BH * TT * DH];
__device__ __half g_Vl [(size_t)BH * TT * DH];
__device__ __half g_Svh[(size_t)BH * TT * DH];

__device__ __forceinline__ uint32_t smem_u32(const void* p) {
    uint32_t a;
    asm("{ .reg .u64 t; cvta.to.shared.u64 t, %1; cvt.u32.u64 %0, t; }"
        : "=r"(a) : "l"(p));
    return a;
}

#define LDSM4(r, addr) \
    asm volatile("ldmatrix.sync.aligned.m8n8.x4.shared.b16 {%0,%1,%2,%3}, [%4];" \
        : "=r"((r)[0]), "=r"((r)[1]), "=r"((r)[2]), "=r"((r)[3]) : "r"(addr))

#define MMA16816(d, a, b0, b1) \
    asm volatile("mma.sync.aligned.m16n8k16.row.col.f32.f16.f16.f32 " \
        "{%0,%1,%2,%3},{%4,%5,%6,%7},{%8,%9},{%0,%1,%2,%3};" \
        : "+f"((d)[0]), "+f"((d)[1]), "+f"((d)[2]), "+f"((d)[3]) \
        : "r"((a)[0]), "r"((a)[1]), "r"((a)[2]), "r"((a)[3]), "r"(b0), "r"(b1))

#define LDBH 144   // bytes per smem fp16 tile row (64 halfs + 16B pad)

// ============================================================================
// Kernel 1: normalize rows -> Vh/Vl (fp16 split), Sv = V*S via mma.sync,
// Svh = fp16(Sv). grid (NT, BH), 256 threads (8 warps, m16 each).
// ============================================================================
#define Q_BSH 0                  // S^T hi  (64 x 64 fp16)  9216 B
#define Q_BSL 9216               // S^T lo                   9216 B
#define Q_VH  18432              // V hi (128 x 64)         18432 B
#define Q_VL  36864              // V lo                    18432 B
#define SMEM_PREP 55296

__global__ __launch_bounds__(256) void prep_kernel(const float* __restrict__ x,
                                                   const float* __restrict__ A) {
    extern __shared__ char sp[];
    const uint32_t sb = smem_u32(sp);
    const int tid  = threadIdx.x;
    const int warp = tid >> 5;
    const int lane = tid & 31;
    const int bh = blockIdx.y;
    const int b  = bh / HH;
    const int h  = bh % HH;
    const int t0c = blockIdx.x * 128;

    // Bs[e][d] = S^T[e][d] = A[d][e] - A[e][d], split hi/lo fp16
    const float* Ah = A + (size_t)h * DH * DH;
    for (int idx = tid; idx < DH * DH; idx += 256) {
        const int e = idx >> 6, d = idx & 63;
        const float s = Ah[d * DH + e] - Ah[e * DH + d];
        const __half hi = __float2half_rn(s);
        const __half lo = __float2half_rn(s - __half2float(hi));
        *(__half*)(sp + Q_BSH + e * LDBH + d * 2) = hi;
        *(__half*)(sp + Q_BSL + e * LDBH + d * 2) = lo;
    }

    // normalize 16 rows per warp, write Vh/Vl (global + smem)
    #pragma unroll
    for (int g = 0; g < 4; ++g) {
        #pragma unroll
        for (int r = 0; r < 4; ++r) {
            const int lr   = warp * 16 + g * 4 + r;
            const int trow = t0c + lr;
            float2 v = *(const float2*)(x + ((size_t)(b * TT + trow)) * DD + h * DH + 2 * lane);
            float ss = v.x * v.x + v.y * v.y;
            #pragma unroll
            for (int o = 16; o; o >>= 1) ss += __shfl_xor_sync(0xffffffffu, ss, o);
            const float sc = 1.0f / fmaxf(sqrtf(ss), 1e-12f);
            v.x *= sc; v.y *= sc;
            const __half hx = __float2half_rn(v.x);
            const __half hy = __float2half_rn(v.y);
            const __half2 H(hx, hy);
            const __half2 L = __floats2half2_rn(v.x - __half2float(hx),
                                                v.y - __half2float(hy));
            const size_t gofs = ((size_t)bh * TT + trow) * DH + 2 * lane;
            *(__half2*)&g_Vh[gofs] = H;
            *(__half2*)&g_Vl[gofs] = L;
            *(__half2*)(sp + Q_VH + lr * LDBH + lane * 4) = H;
            *(__half2*)(sp + Q_VL + lr * LDBH + lane * 4) = L;
        }
    }
    __syncthreads();

    // Sv = V @ S via mma: A = Vh (m16k64 per warp), B = Bs hi/lo (n64 k64)
    const uint32_t aB = sb + Q_VH + (uint32_t)(warp * 16 + (lane & 15)) * LDBH
                      + ((uint32_t)(lane >> 4)) * 16;
    const uint32_t bB = sb + Q_BSH + (uint32_t)((lane & 7) | ((lane >> 1) & 8)) * LDBH
                      + ((uint32_t)(lane & 8)) * 2;

    float acc[8][4];
    #pragma unroll
    for (int q = 0; q < 8; ++q)
        #pragma unroll
        for (int c = 0; c < 4; ++c) acc[q][c] = 0.f;

    #pragma unroll
    for (int kk = 0; kk < 4; ++kk) {
        uint32_t ah[4];
        LDSM4(ah, aB + kk * 32);
        #pragma unroll
        for (int n16 = 0; n16 < 4; ++n16) {
            uint32_t bhf[4], blf[4];
            LDSM4(bhf, bB + n16 * 16 * LDBH + kk * 32);
            LDSM4(blf, bB + (Q_BSL - Q_BSH) + n16 * 16 * LDBH + kk * 32);
            MMA16816(acc[2 * n16],     ah, bhf[0], bhf[1]);
            MMA16816(acc[2 * n16 + 1], ah, bhf[2], bhf[3]);
            MMA16816(acc[2 * n16],     ah, blf[0], blf[1]);
            MMA16816(acc[2 * n16 + 1], ah, blf[2], blf[3]);
        }
    }

    // store Svh (fp16)
    const int r = warp * 16 + (lane >> 2);
    #pragma unroll
    for (int q = 0; q < 8; ++q) {
        const int col = q * 8 + (lane & 3) * 2;
        const __half2 h0 = __floats2half2_rn(acc[q][0], acc[q][1]);
        const __half2 h1 = __floats2half2_rn(acc[q][2], acc[q][3]);
        *(__half2*)&g_Svh[((size_t)bh * TT + t0c + r) * DH + col]     = h0;
        *(__half2*)&g_Svh[((size_t)bh * TT + t0c + r + 8) * DH + col] = h1;
    }
}

// ============================================================================
// Kernel 2: fp16 mma wedge, 2-pass (Ah*Bh + Ah*Bl), tiles loaded verbatim
// from fp16 scratch, per-warp coalesced epilogue with streaming stores.
// grid (NPAIRS, BH), 256 threads, 2 CTA/SM.
// ============================================================================
#define T_AH   0
#define T_BH   18432
#define T_BL   36864
#define P_STG  55296
#define WSLICE 4608
#define SMEM_WEDGE (P_STG + 8*WSLICE)    // 92160

__device__ __forceinline__ void copy_tile(char* dst, const __half* __restrict__ src,
                                          int tid) {
    #pragma unroll
    for (int p = 0; p < 4; ++p) {
        const int f   = p * 256 + tid;      // uint4 index 0..1023
        const int row = f >> 3;
        const int c   = f & 7;
        *(uint4*)(dst + row * LDBH + c * 16) = ((const uint4*)src)[f];
    }
}

__global__ __launch_bounds__(256, 2) void wedge_mma(float* __restrict__ out) {
    extern __shared__ char sm[];
    const uint32_t sb = smem_u32(sm);
    const int tid  = threadIdx.x;
    const int w    = tid >> 5;
    const int lane = tid & 31;
    const int bh   = blockIdx.y;
    const int wm   = w >> 2;     // 0..1
    const int wn   = w & 3;      // 0..3

    int p = blockIdx.x;
    int i = 0;
    while (p >= NT - i) { p -= NT - i; ++i; }
    const int j  = i + p;
    const int i0 = i * TILE;
    const int j0 = j * TILE;

    float* outb = out + (size_t)bh * TT * TT;

    copy_tile(sm + T_AH, g_Svh + ((size_t)bh * TT + i0) * DH, tid);
    copy_tile(sm + T_BH, g_Vh  + ((size_t)bh * TT + j0) * DH, tid);
    copy_tile(sm + T_BL, g_Vl  + ((size_t)bh * TT + j0) * DH, tid);
    __syncthreads();

    const uint32_t aB = sb + T_AH + (uint32_t)(wm * 64 + (lane & 15)) * LDBH
                      + ((uint32_t)(lane >> 4)) * 16;
    const uint32_t bn = (uint32_t)((lane & 7) | ((lane >> 1) & 8));
    const uint32_t bB = sb + T_BH + ((uint32_t)(wn * 32) + bn) * LDBH
                      + ((uint32_t)(lane & 8)) * 2;

    float acc[4][4][4];
    #pragma unroll
    for (int mt = 0; mt < 4; ++mt)
        #pragma unroll
        for (int nt = 0; nt < 4; ++nt)
            #pragma unroll
            for (int q = 0; q < 4; ++q) acc[mt][nt][q] = 0.f;

    #pragma unroll
    for (int kk = 0; kk < 4; ++kk) {
        uint32_t bh0[4], bh1[4], bl0[4], bl1[4];
        LDSM4(bh0, bB + kk * 32);
        LDSM4(bh1, bB + 16 * LDBH + kk * 32);
        LDSM4(bl0, bB + (T_BL - T_BH) + kk * 32);
        LDSM4(bl1, bB + (T_BL - T_BH) + 16 * LDBH + kk * 32);
        #pragma unroll
        for (int mt = 0; mt < 4; ++mt) {
            uint32_t ah[4];
            LDSM4(ah, aB + mt * 16 * LDBH + kk * 32);
            MMA16816(acc[mt][0], ah, bh0[0], bh0[1]);
            MMA16816(acc[mt][1], ah, bh0[2], bh0[3]);
            MMA16816(acc[mt][2], ah, bh1[0], bh1[1]);
            MMA16816(acc[mt][3], ah, bh1[2], bh1[3]);
            MMA16816(acc[mt][0], ah, bl0[0], bl0[1]);
            MMA16816(acc[mt][1], ah, bl0[2], bl0[3]);
            MMA16816(acc[mt][2], ah, bl1[0], bl1[1]);
            MMA16816(acc[mt][3], ah, bl1[2], bl1[3]);
        }
    }

    // ---- per-warp epilogue (no CTA barriers) ----
    float* stg = (float*)(sm + P_STG + w * WSLICE);
    const int rql = lane >> 2;
    const int cql = (lane & 3) * 2;

    // normal tile (i,j)
    #pragma unroll
    for (int mt = 0; mt < 4; ++mt) {
        #pragma unroll
        for (int nt = 0; nt < 4; ++nt) {
            const int col = nt * 8 + cql;
            *(float2*)&stg[rql * 40 + col]       = make_float2(acc[mt][nt][0], acc[mt][nt][1]);
            *(float2*)&stg[(rql + 8) * 40 + col] = make_float2(acc[mt][nt][2], acc[mt][nt][3]);
        }
        __syncwarp();
        #pragma unroll
        for (int pp = 0; pp < 4; ++pp) {
            const int r = pp * 4 + (lane >> 3);
            const float4 v = *(const float4*)&stg[r * 40 + (lane & 7) * 4];
            const int grow = i0 + wm * 64 + mt * 16 + r;
            __stcs((float4*)&outb[(size_t)grow * TT + j0 + wn * 32 + (lane & 7) * 4], v);
        }
        __syncwarp();
    }

    // mirror tile (j,i) = -transpose
    if (i != j) {
        #pragma unroll
        for (int cc = 0; cc < 2; ++cc) {
            #pragma unroll
            for (int ntl = 0; ntl < 2; ++ntl) {
                const int nt = cc * 2 + ntl;
                const int c0 = ntl * 8 + cql;
                #pragma unroll
                for (int mt = 0; mt < 4; ++mt) {
                    const int rbase = mt * 16 + rql;
                    stg[c0 * 72 + rbase]           = -acc[mt][nt][0];
                    stg[(c0 + 1) * 72 + rbase]     = -acc[mt][nt][1];
                    stg[c0 * 72 + rbase + 8]       = -acc[mt][nt][2];
                    stg[(c0 + 1) * 72 + rbase + 8] = -acc[mt][nt][3];
                }
            }
            __syncwarp();
            #pragma unroll
            for (int pp = 0; pp < 8; ++pp) {
                const int c = pp * 2 + (lane >> 4);
                const float4 v = *(const float4*)&stg[c * 72 + (lane & 15) * 4];
                const int grow = j0 + wn * 32 + cc * 16 + c;
                __stcs((float4*)&outb[(size_t)grow * TT + i0 + wm * 64 + (lane & 15) * 4], v);
            }
            __syncwarp();
        }
    }
}

// ============================================================================
extern "C" void kernel_launch(void* const* d_in, const int* in_sizes, int n_in,
                              void* d_out, int out_size) {
    (void)in_sizes; (void)n_in; (void)out_size;
    const float* x = (const float*)d_in[0];
    const float* A = (const float*)d_in[1];
    float* out = (float*)d_out;

    cudaFuncSetAttribute(prep_kernel, cudaFuncAttributeMaxDynamicSharedMemorySize, SMEM_PREP);
    prep_kernel<<<dim3(NT, BH), 256, SMEM_PREP>>>(x, A);

    cudaFuncSetAttribute(wedge_mma, cudaFuncAttributeMaxDynamicSharedMemorySize, SMEM_WEDGE);
    wedge_mma<<<dim3(NPAIRS, BH), 256, SMEM_WEDGE>>>(out);
}

// round 8
// speedup vs baseline: 2.6585x; 1.0338x over previous
#include <cuda_runtime.h>
#include <cuda_fp16.h>
#include <cstdint>

#define BB   2
#define TT   2048
#define HH   16
#define DH   64
#define DD   1024
#define BH   (BB*HH)
#define TILE 128
#define NT   (TT/TILE)
#define NPAIRS (NT*(NT+1)/2)

// fp16 scratch (8 MB each, 24 MB total -> L2 resident)
__device__ __half g_Vh [(size_t)BH * TT * DH];
__device__ __half g_Vl [(size_t)BH * TT * DH];
__device__ __half g_Svh[(size_t)BH * TT * DH];

__device__ __forceinline__ uint32_t smem_u32(const void* p) {
    uint32_t a;
    asm("{ .reg .u64 t; cvta.to.shared.u64 t, %1; cvt.u32.u64 %0, t; }"
        : "=r"(a) : "l"(p));
    return a;
}

#define LDSM4(r, addr) \
    asm volatile("ldmatrix.sync.aligned.m8n8.x4.shared.b16 {%0,%1,%2,%3}, [%4];" \
        : "=r"((r)[0]), "=r"((r)[1]), "=r"((r)[2]), "=r"((r)[3]) : "r"(addr))

#define MMA16816(d, a, b0, b1) \
    asm volatile("mma.sync.aligned.m16n8k16.row.col.f32.f16.f16.f32 " \
        "{%0,%1,%2,%3},{%4,%5,%6,%7},{%8,%9},{%0,%1,%2,%3};" \
        : "+f"((d)[0]), "+f"((d)[1]), "+f"((d)[2]), "+f"((d)[3]) \
        : "r"((a)[0]), "r"((a)[1]), "r"((a)[2]), "r"((a)[3]), "r"(b0), "r"(b1))

#define LDBH 144   // bytes per smem fp16 tile row (64 halfs + 16B pad)

// ============================================================================
// Kernel 1: normalize rows -> Vh/Vl, Sv = V*S via mma.sync, Svh = fp16(Sv).
// A staged coalesced into padded smem (stride 65) before forming S.
// grid (NT, BH), 256 threads.
// ============================================================================
#define Q_BSH 0                  // S^T hi (64x64 fp16)  9216 B
#define Q_BSL 9216               // S^T lo                9216 B
#define Q_VH  18432              // V hi (128x64)        18432 B
#define Q_VL  36864              // V lo                 18432 B
#define Q_AS  55296              // A staged, 64x65 f32  16640 B
#define SMEM_PREP 71936

__global__ __launch_bounds__(256) void prep_kernel(const float* __restrict__ x,
                                                   const float* __restrict__ A) {
    extern __shared__ char sp[];
    const uint32_t sb = smem_u32(sp);
    float* As = (float*)(sp + Q_AS);
    const int tid  = threadIdx.x;
    const int warp = tid >> 5;
    const int lane = tid & 31;
    const int bh = blockIdx.y;
    const int b  = bh / HH;
    const int h  = bh % HH;
    const int t0c = blockIdx.x * 128;

    // stage A coalesced (float4 reads), padded stride 65
    {
        const float4* Ah4 = (const float4*)(A + (size_t)h * DH * DH);
        #pragma unroll
        for (int p = 0; p < 4; ++p) {
            const int f  = p * 256 + tid;       // float4 idx 0..1023
            const int d  = f >> 4;
            const int c4 = (f & 15) * 4;
            const float4 v = Ah4[f];
            As[d * 65 + c4 + 0] = v.x;
            As[d * 65 + c4 + 1] = v.y;
            As[d * 65 + c4 + 2] = v.z;
            As[d * 65 + c4 + 3] = v.w;
        }
    }
    __syncthreads();

    // Bs[e][d] = S^T[e][d] = A[d][e] - A[e][d], split hi/lo fp16
    #pragma unroll
    for (int p = 0; p < 16; ++p) {
        const int idx = p * 256 + tid;
        const int e = idx >> 6, d = idx & 63;
        const float s = As[d * 65 + e] - As[e * 65 + d];
        const __half hi = __float2half_rn(s);
        const __half lo = __float2half_rn(s - __half2float(hi));
        *(__half*)(sp + Q_BSH + e * LDBH + d * 2) = hi;
        *(__half*)(sp + Q_BSL + e * LDBH + d * 2) = lo;
    }

    // normalize 16 rows per warp, write Vh/Vl (global + smem)
    #pragma unroll
    for (int g = 0; g < 4; ++g) {
        #pragma unroll
        for (int r = 0; r < 4; ++r) {
            const int lr   = warp * 16 + g * 4 + r;
            const int trow = t0c + lr;
            float2 v = *(const float2*)(x + ((size_t)(b * TT + trow)) * DD + h * DH + 2 * lane);
            float ss = v.x * v.x + v.y * v.y;
            #pragma unroll
            for (int o = 16; o; o >>= 1) ss += __shfl_xor_sync(0xffffffffu, ss, o);
            const float sc = 1.0f / fmaxf(sqrtf(ss), 1e-12f);
            v.x *= sc; v.y *= sc;
            const __half hx = __float2half_rn(v.x);
            const __half hy = __float2half_rn(v.y);
            const __half2 H(hx, hy);
            const __half2 L = __floats2half2_rn(v.x - __half2float(hx),
                                                v.y - __half2float(hy));
            const size_t gofs = ((size_t)bh * TT + trow) * DH + 2 * lane;
            *(__half2*)&g_Vh[gofs] = H;
            *(__half2*)&g_Vl[gofs] = L;
            *(__half2*)(sp + Q_VH + lr * LDBH + lane * 4) = H;
            *(__half2*)(sp + Q_VL + lr * LDBH + lane * 4) = L;
        }
    }
    __syncthreads();

    // Sv = V @ S via mma (2 passes: Vh*Sh + Vh*Sl)
    const uint32_t aB = sb + Q_VH + (uint32_t)(warp * 16 + (lane & 15)) * LDBH
                      + ((uint32_t)(lane >> 4)) * 16;
    const uint32_t bB = sb + Q_BSH + (uint32_t)((lane & 7) | ((lane >> 1) & 8)) * LDBH
                      + ((uint32_t)(lane & 8)) * 2;

    float acc[8][4];
    #pragma unroll
    for (int q = 0; q < 8; ++q)
        #pragma unroll
        for (int c = 0; c < 4; ++c) acc[q][c] = 0.f;

    #pragma unroll
    for (int kk = 0; kk < 4; ++kk) {
        uint32_t ah[4];
        LDSM4(ah, aB + kk * 32);
        #pragma unroll
        for (int n16 = 0; n16 < 4; ++n16) {
            uint32_t bhf[4], blf[4];
            LDSM4(bhf, bB + n16 * 16 * LDBH + kk * 32);
            LDSM4(blf, bB + (Q_BSL - Q_BSH) + n16 * 16 * LDBH + kk * 32);
            MMA16816(acc[2 * n16],     ah, bhf[0], bhf[1]);
            MMA16816(acc[2 * n16 + 1], ah, bhf[2], bhf[3]);
            MMA16816(acc[2 * n16],     ah, blf[0], blf[1]);
            MMA16816(acc[2 * n16 + 1], ah, blf[2], blf[3]);
        }
    }

    const int r = warp * 16 + (lane >> 2);
    #pragma unroll
    for (int q = 0; q < 8; ++q) {
        const int col = q * 8 + (lane & 3) * 2;
        const __half2 h0 = __floats2half2_rn(acc[q][0], acc[q][1]);
        const __half2 h1 = __floats2half2_rn(acc[q][2], acc[q][3]);
        *(__half2*)&g_Svh[((size_t)bh * TT + t0c + r) * DH + col]     = h0;
        *(__half2*)&g_Svh[((size_t)bh * TT + t0c + r + 8) * DH + col] = h1;
    }
}

// ============================================================================
// Kernel 2: fp16 mma wedge, 2-pass, verbatim fp16 tile loads, per-warp
// coalesced epilogue (mirror stage stride 76 = conflict-free).
// grid (NPAIRS, BH), 256 threads, 2 CTA/SM.
// ============================================================================
#define T_AH   0
#define T_BH   18432
#define T_BL   36864
#define P_STG  55296
#define WSLICE 4864
#define SMEM_WEDGE (P_STG + 8*WSLICE)    // 94208

__device__ __forceinline__ void copy_tile(char* dst, const __half* __restrict__ src,
                                          int tid) {
    #pragma unroll
    for (int p = 0; p < 4; ++p) {
        const int f   = p * 256 + tid;
        const int row = f >> 3;
        const int c   = f & 7;
        *(uint4*)(dst + row * LDBH + c * 16) = ((const uint4*)src)[f];
    }
}

__global__ __launch_bounds__(256, 2) void wedge_mma(float* __restrict__ out) {
    extern __shared__ char sm[];
    const uint32_t sb = smem_u32(sm);
    const int tid  = threadIdx.x;
    const int w    = tid >> 5;
    const int lane = tid & 31;
    const int bh   = blockIdx.y;
    const int wm   = w >> 2;
    const int wn   = w & 3;

    int p = blockIdx.x;
    int i = 0;
    while (p >= NT - i) { p -= NT - i; ++i; }
    const int j  = i + p;
    const int i0 = i * TILE;
    const int j0 = j * TILE;

    float* outb = out + (size_t)bh * TT * TT;

    copy_tile(sm + T_AH, g_Svh + ((size_t)bh * TT + i0) * DH, tid);
    copy_tile(sm + T_BH, g_Vh  + ((size_t)bh * TT + j0) * DH, tid);
    copy_tile(sm + T_BL, g_Vl  + ((size_t)bh * TT + j0) * DH, tid);
    __syncthreads();

    const uint32_t aB = sb + T_AH + (uint32_t)(wm * 64 + (lane & 15)) * LDBH
                      + ((uint32_t)(lane >> 4)) * 16;
    const uint32_t bn = (uint32_t)((lane & 7) | ((lane >> 1) & 8));
    const uint32_t bB = sb + T_BH + ((uint32_t)(wn * 32) + bn) * LDBH
                      + ((uint32_t)(lane & 8)) * 2;

    float acc[4][4][4];
    #pragma unroll
    for (int mt = 0; mt < 4; ++mt)
        #pragma unroll
        for (int nt = 0; nt < 4; ++nt)
            #pragma unroll
            for (int q = 0; q < 4; ++q) acc[mt][nt][q] = 0.f;

    #pragma unroll
    for (int kk = 0; kk < 4; ++kk) {
        uint32_t bh0[4], bh1[4], bl0[4], bl1[4];
        LDSM4(bh0, bB + kk * 32);
        LDSM4(bh1, bB + 16 * LDBH + kk * 32);
        LDSM4(bl0, bB + (T_BL - T_BH) + kk * 32);
        LDSM4(bl1, bB + (T_BL - T_BH) + 16 * LDBH + kk * 32);
        #pragma unroll
        for (int mt = 0; mt < 4; ++mt) {
            uint32_t ah[4];
            LDSM4(ah, aB + mt * 16 * LDBH + kk * 32);
            MMA16816(acc[mt][0], ah, bh0[0], bh0[1]);
            MMA16816(acc[mt][1], ah, bh0[2], bh0[3]);
            MMA16816(acc[mt][2], ah, bh1[0], bh1[1]);
            MMA16816(acc[mt][3], ah, bh1[2], bh1[3]);
            MMA16816(acc[mt][0], ah, bl0[0], bl0[1]);
            MMA16816(acc[mt][1], ah, bl0[2], bl0[3]);
            MMA16816(acc[mt][2], ah, bl1[0], bl1[1]);
            MMA16816(acc[mt][3], ah, bl1[2], bl1[3]);
        }
    }

    // ---- per-warp epilogue (no CTA barriers) ----
    float* stg = (float*)(sm + P_STG + w * WSLICE);
    const int rql = lane >> 2;
    const int cql = (lane & 3) * 2;

    // normal tile (i,j)
    #pragma unroll
    for (int mt = 0; mt < 4; ++mt) {
        #pragma unroll
        for (int nt = 0; nt < 4; ++nt) {
            const int col = nt * 8 + cql;
            *(float2*)&stg[rql * 40 + col]       = make_float2(acc[mt][nt][0], acc[mt][nt][1]);
            *(float2*)&stg[(rql + 8) * 40 + col] = make_float2(acc[mt][nt][2], acc[mt][nt][3]);
        }
        __syncwarp();
        #pragma unroll
        for (int pp = 0; pp < 4; ++pp) {
            const int r = pp * 4 + (lane >> 3);
            const float4 v = *(const float4*)&stg[r * 40 + (lane & 7) * 4];
            const int grow = i0 + wm * 64 + mt * 16 + r;
            __stcs((float4*)&outb[(size_t)grow * TT + j0 + wn * 32 + (lane & 7) * 4], v);
        }
        __syncwarp();
    }

    // mirror tile (j,i) = -transpose, stage stride 76 (conflict-free banks)
    if (i != j) {
        #pragma unroll
        for (int cc = 0; cc < 2; ++cc) {
            #pragma unroll
            for (int ntl = 0; ntl < 2; ++ntl) {
                const int nt = cc * 2 + ntl;
                const int c0 = ntl * 8 + cql;
                #pragma unroll
                for (int mt = 0; mt < 4; ++mt) {
                    const int rbase = mt * 16 + rql;
                    stg[c0 * 76 + rbase]           = -acc[mt][nt][0];
                    stg[(c0 + 1) * 76 + rbase]     = -acc[mt][nt][1];
                    stg[c0 * 76 + rbase + 8]       = -acc[mt][nt][2];
                    stg[(c0 + 1) * 76 + rbase + 8] = -acc[mt][nt][3];
                }
            }
            __syncwarp();
            #pragma unroll
            for (int pp = 0; pp < 8; ++pp) {
                const int c = pp * 2 + (lane >> 4);
                const float4 v = *(const float4*)&stg[c * 76 + (lane & 15) * 4];
                const int grow = j0 + wn * 32 + cc * 16 + c;
                __stcs((float4*)&outb[(size_t)grow * TT + i0 + wm * 64 + (lane & 15) * 4], v);
            }
            __syncwarp();
        }
    }
}

// ============================================================================
extern "C" void kernel_launch(void* const* d_in, const int* in_sizes, int n_in,
                              void* d_out, int out_size) {
    (void)in_sizes; (void)n_in; (void)out_size;
    const float* x = (const float*)d_in[0];
    const float* A = (const float*)d_in[1];
    float* out = (float*)d_out;

    cudaFuncSetAttribute(prep_kernel, cudaFuncAttributeMaxDynamicSharedMemorySize, SMEM_PREP);
    prep_kernel<<<dim3(NT, BH), 256, SMEM_PREP>>>(x, A);

    cudaFuncSetAttribute(wedge_mma, cudaFuncAttributeMaxDynamicSharedMemorySize, SMEM_WEDGE);
    wedge_mma<<<dim3(NPAIRS, BH), 256, SMEM_WEDGE>>>(out);
}